// round 8
// baseline (speedup 1.0000x reference)
#include <cuda_runtime.h>
#include <math.h>

#define NB      1024
#define LSCALE  128.0f
#define KPRE    300
#define KOUT    10
#define CAP     768
#define SEL     512
#define NSEG    8
#define SEGSZ   512
#define RAW_T0  420
#define PPI     12
#define NPARTS  192

// global scratch (static device globals: no allocation)
__device__ float  g_sc[NPARTS*CAP];
__device__ int    g_ix[NPARTS*CAP];
__device__ float4 g_bx[NPARTS*CAP];
__device__ int    g_cnt[NPARTS];
__device__ int    g_arrive[64];       // zero-init; merge CTA resets to 0

struct Ptrs {
    const float* cls[4];
    const float* box[4];
    const float* anc[4];
};

// 192 part-CTAs select per-part exact top-300-valid (logit domain) into
// global scratch; the last CTA to arrive in each (batch,level) group merges:
// histogram cut -> <=512 keys -> bitonic sort (key preserves lax.top_k tie
// order) -> greedy NMS -> output. Single launch.
__global__ __launch_bounds__(512) void detect_kernel(Ptrs P, float* out, int out_size) {
    const int pid = blockIdx.x;
    const int b  = pid / PPI;
    const int pp = pid % PPI;
    int lvl, partIdx;
    if      (pp < 8)   { lvl = 0; partIdx = pp; }
    else if (pp < 10)  { lvl = 1; partIdx = pp - 8; }
    else if (pp == 10) { lvl = 2; partIdx = 0; }
    else               { lvl = 3; partIdx = 0; }
    const int HW    = 16384 >> (2*lvl);
    const int N     = 9 * HW;
    const int PARTN = (lvl==0) ? N/8 : (lvl==1) ? N/2 : N;   // 18432,18432,9216,2304
    const int j0    = partIdx * PARTN;
    const int flBK  = (lvl<=1) ? 128 : (lvl==2) ? 64 : 0;
    const float floorVal = (float)flBK * (1.0f/128.0f);
    const float* cls  = P.cls[lvl] + (size_t)b * N + j0;
    const float* boxp = P.box[lvl];
    const float* anc  = P.anc[lvl];
    const int tid = threadIdx.x, wid = tid >> 5, lane = tid & 31;

    __shared__ int hist[NB];
    __shared__ union {
        struct { float cval[NSEG*SEGSZ]; int cidx[NSEG*SEGSZ]; } sel;   // 32KB
        struct {
            unsigned long long key[SEL];
            float x1[KPRE], y1[KPRE], x2[KPRE], y2[KPRE], area[KPRE], logit[KPRE];
        } mrg;                                                          // 11.3KB
    } U;
    __shared__ int wtot[16];
    __shared__ int s_seg[NSEG];
    __shared__ int s_cnt, s_cut, s_scnt, s_next, s_nk, s_last;
    __shared__ unsigned keepw[10];
    __shared__ int s_pc[8];

    // ---------------- select phase ----------------
    for (int i = tid; i < NB; i += 512) hist[i] = 0;
    if (tid < NSEG) s_seg[tid] = 0;
    if (tid == 0) s_cnt = 0;
    __syncthreads();

    const int n4 = PARTN >> 2;
    const float4* cls4 = (const float4*)cls;
    const int seg = wid & (NSEG-1);

    auto above_floor = [&](float x) -> bool {
        return (flBK == 0) ? (x > 0.0f) : (x >= floorVal);
    };
    auto proc = [&](float4 v, int i4) {
        float mx = fmaxf(fmaxf(v.x, v.y), fmaxf(v.z, v.w));
        if (above_floor(mx)) {
            float xs[4] = {v.x, v.y, v.z, v.w};
            #pragma unroll
            for (int c = 0; c < 4; c++) {
                float x = xs[c];
                if (above_floor(x)) {
                    int bk = (int)(x * LSCALE); bk = bk > NB-1 ? NB-1 : bk;
                    atomicAdd(&hist[bk], 1);
                    int p = atomicAdd(&s_seg[seg], 1);
                    if (p < SEGSZ) { U.sel.cval[seg*SEGSZ + p] = x; U.sel.cidx[seg*SEGSZ + p] = i4*4 + c; }
                }
            }
        }
    };
    {
        int i = tid;
        for (; i + 7*512 < n4; i += 8*512) {
            float4 v0 = cls4[i];         float4 v1 = cls4[i + 512];
            float4 v2 = cls4[i + 1024];  float4 v3 = cls4[i + 1536];
            float4 v4 = cls4[i + 2048];  float4 v5 = cls4[i + 2560];
            float4 v6 = cls4[i + 3072];  float4 v7 = cls4[i + 3584];
            proc(v0, i);        proc(v1, i + 512);
            proc(v2, i + 1024); proc(v3, i + 1536);
            proc(v4, i + 2048); proc(v5, i + 2560);
            proc(v6, i + 3072); proc(v7, i + 3584);
        }
        for (; i < n4; i += 512) proc(cls4[i], i);
    }
    __syncthreads();

    bool cacheOK = true;
    #pragma unroll
    for (int s = 0; s < NSEG; s++) cacheOK = cacheOK && (s_seg[s] <= SEGSZ);

    // suffix count strictly after this thread's bucket pair [2t,2t+1]
    auto computeAbove = [&]() -> int {
        __syncthreads();
        int h = hist[2*tid] + hist[2*tid+1];
        int v = h;
        #pragma unroll
        for (int off = 1; off < 32; off <<= 1) {
            int t2 = __shfl_down_sync(0xFFFFFFFFu, v, off);
            if (lane + off < 32) v += t2;
        }
        if (lane == 0) wtot[wid] = v;
        __syncthreads();
        int tail = 0;
        for (int w = wid + 1; w < 16; w++) tail += wtot[w];
        return (v - h) + tail;
    };

    auto decode_store = [&](float x, int jrel) {
        int j = j0 + jrel;
        int a = j / HW;
        int rem = j - a*HW;
        const float* bp = boxp + ((size_t)(b*9 + a) * 4) * HW + rem;
        float d0 = bp[0], d1 = bp[HW], d2 = bp[2*HW], d3 = bp[3*HW];
        float4 an = ((const float4*)anc)[j];
        float w = an.z - an.x, h = an.w - an.y;
        float cx = an.x + 0.5f*w, cy = an.y + 0.5f*h;
        d0 = fminf(fmaxf(d0, -2.0f), 2.0f);
        d1 = fminf(fmaxf(d1, -2.0f), 2.0f);
        d2 = fminf(fmaxf(d2, -2.0f), 2.0f);
        d3 = fminf(fmaxf(d3, -2.0f), 2.0f);
        float px = cx + d0*w, py = cy + d1*h;
        float pw = w * expf(d2), ph = h * expf(d3);
        float x1 = fminf(fmaxf(px - 0.5f*pw, 0.0f), 1024.0f);
        float y1 = fminf(fmaxf(py - 0.5f*ph, 0.0f), 1024.0f);
        float x2 = fminf(fmaxf(px + 0.5f*pw, 0.0f), 1024.0f);
        float y2 = fminf(fmaxf(py + 0.5f*ph, 0.0f), 1024.0f);
        float bw = x2 - x1, bh = y2 - y1;
        if (bw > 1.0f && bh > 1.0f && bw < 2000.0f && bh < 2000.0f) {
            int pos = atomicAdd(&s_cnt, 1);
            if (pos < CAP) {
                g_sc[pid*CAP + pos] = x;
                g_ix[pid*CAP + pos] = j;
                g_bx[pid*CAP + pos] = make_float4(x1, y1, x2, y2);
            }
        }
    };

    int above = computeAbove();
    bool histFull = (flBK == 0);
    int curCut = NB;
    int rawTarget = RAW_T0;
    while (true) {
        if (tid == 0) s_cut = 0;
        __syncthreads();
        {
            int cum1 = above + hist[2*tid+1];
            int cum0 = cum1 + hist[2*tid];
            int c = -1;
            if (2*tid+1 < curCut && cum1 >= rawTarget && above < rawTarget) c = 2*tid+1;
            if (2*tid   < curCut && cum0 >= rawTarget && cum1  < rawTarget) c = 2*tid;
            if (c >= 0) s_cut = c;     // unique crossing bucket
        }
        __syncthreads();
        int newCut = s_cut;

        if (!histFull && newCut < flBK) {
            // cold path: extend histogram below the floor (exactness guard)
            for (int i = tid; i < n4; i += 512) {
                float4 v = cls4[i];
                float xs[4] = {v.x, v.y, v.z, v.w};
                for (int c = 0; c < 4; c++) {
                    float x = xs[c];
                    if (x > 0.0f && !above_floor(x)) {
                        int bk = (int)(x * LSCALE); bk = bk > NB-1 ? NB-1 : bk;
                        atomicAdd(&hist[bk], 1);
                    }
                }
            }
            histFull = true;
            above = computeAbove();
            continue;
        }

        if (cacheOK && newCut >= flBK) {
            for (int t = tid; t < NSEG*SEGSZ; t += 512) {
                int sg = t / SEGSZ, o = t - sg*SEGSZ;
                if (o < s_seg[sg]) {
                    float x = U.sel.cval[t];
                    int bk = (int)(x * LSCALE); bk = bk > NB-1 ? NB-1 : bk;
                    if (bk >= newCut && bk < curCut) decode_store(x, U.sel.cidx[t]);
                }
            }
        } else {
            // exact fallback: rescan global for the band
            for (int i = tid; i < n4; i += 512) {
                float4 v = cls4[i];
                float xs[4] = {v.x, v.y, v.z, v.w};
                for (int c = 0; c < 4; c++) {
                    float x = xs[c];
                    if (x > 0.0f) {
                        int bk = (int)(x * LSCALE); bk = bk > NB-1 ? NB-1 : bk;
                        if (bk >= newCut && bk < curCut) decode_store(x, i*4 + c);
                    }
                }
            }
        }
        __syncthreads();
        int cnt = s_cnt;
        curCut = newCut;
        if (cnt >= KPRE || curCut == 0) break;
        rawTarget += (KPRE - cnt) + 32;
        __syncthreads();
    }
    if (tid == 0) g_cnt[pid] = (s_cnt < CAP) ? s_cnt : CAP;

    // ---------------- arrival: last CTA in group merges ----------------
    __threadfence();
    __syncthreads();
    const int grpOffA[4] = {0, 8, 10, 11};
    const int npA[4]     = {8, 2, 1, 1};
    const int grp = b*4 + lvl;
    const int np  = npA[lvl];
    if (tid == 0) {
        int old = atomicAdd(&g_arrive[grp], 1);
        s_last = (old == np - 1);
        if (s_last) atomicExch(&g_arrive[grp], 0);   // reset for next replay
    }
    __syncthreads();
    if (!s_last) return;
    __threadfence();

    // ---------------- merge phase (one CTA per image-level) ----------------
    const int p0 = b*PPI + grpOffA[lvl];
    const bool vF = (out_size >= 3840);
    unsigned char* vB = (unsigned char*)out + 12800;
    const int slot0 = b*40 + lvl*10;
    {
        int base5 = b*200 + lvl*50;
        if (tid < 50) out[base5 + tid] = 0.0f;
        if (tid >= 64 && tid < 74) {
            int k = tid - 64;
            if (vF) out[3200 + slot0 + k] = 0.0f;
            else    vB[slot0 + k] = 0;
        }
    }
    for (int i = tid; i < NB; i += 512) hist[i] = 0;
    if (tid < np) s_pc[tid] = g_cnt[p0 + tid];
    if (tid == 0) { s_scnt = 0; s_cut = 0; s_nk = 0; }
    __syncthreads();

    // histogram over merged part entries (L2-hot)
    for (int k = 0; k < np; k++) {
        int cnt = s_pc[k];
        int base = (p0 + k) * CAP;
        for (int i = tid; i < cnt; i += 512) {
            float x = g_sc[base + i];
            int bk = (int)(x * LSCALE); bk = bk > NB-1 ? NB-1 : bk;
            atomicAdd(&hist[bk], 1);
        }
    }
    __syncthreads();
    {
        int h = hist[2*tid] + hist[2*tid+1];
        int v = h;
        #pragma unroll
        for (int off = 1; off < 32; off <<= 1) {
            int t2 = __shfl_down_sync(0xFFFFFFFFu, v, off);
            if (lane + off < 32) v += t2;
        }
        if (lane == 0) wtot[wid] = v;
        __syncthreads();
        int tail = 0;
        for (int w = wid + 1; w < 16; w++) tail += wtot[w];
        int above2 = (v - h) + tail;
        int cum1 = above2 + hist[2*tid+1];
        int cum0 = cum1 + hist[2*tid];
        if (cum1 >= KPRE && above2 < KPRE) s_cut = 2*tid+1;
        if (cum0 >= KPRE && cum1  < KPRE) s_cut = 2*tid;
    }
    __syncthreads();
    int cut = s_cut;

    // collect superset of top-300: key = score | ~ancidx(18b) | relslot(13b)
    for (int k = 0; k < np; k++) {
        int cnt = s_pc[k];
        int base = (p0 + k) * CAP;
        for (int i = tid; i < cnt; i += 512) {
            float x = g_sc[base + i];
            int bk = (int)(x * LSCALE); bk = bk > NB-1 ? NB-1 : bk;
            if (bk >= cut) {
                int pos = atomicAdd(&s_scnt, 1);
                if (pos < SEL) {
                    unsigned j = (unsigned)g_ix[base + i];
                    int rel = k*CAP + i;
                    unsigned lo = ((262143u - j) << 13) | (unsigned)rel;
                    U.mrg.key[pos] = ((unsigned long long)__float_as_uint(x) << 32)
                                   | (unsigned long long)lo;
                }
            }
        }
    }
    __syncthreads();
    int scnt = s_scnt < SEL ? s_scnt : SEL;
    for (int i = scnt + tid; i < SEL; i += 512) U.mrg.key[i] = 0ull;
    __syncthreads();

    // bitonic sort descending, 512 elems / 512 threads
    {
        unsigned long long key = U.mrg.key[tid];
        __syncthreads();
        #pragma unroll
        for (int k = 2; k <= SEL; k <<= 1) {
            bool segDesc = ((tid & k) == 0);
            #pragma unroll
            for (int j = k >> 1; j > 0; j >>= 1) {
                unsigned long long okey;
                if (j >= 32) {
                    U.mrg.key[tid] = key;
                    __syncthreads();
                    okey = U.mrg.key[tid ^ j];
                    __syncthreads();
                } else {
                    unsigned hi = __shfl_xor_sync(0xFFFFFFFFu, (unsigned)(key >> 32), j);
                    unsigned lo = __shfl_xor_sync(0xFFFFFFFFu, (unsigned)key, j);
                    okey = ((unsigned long long)hi << 32) | lo;
                }
                bool keepMax = (((tid & j) == 0) == segDesc);
                bool take = keepMax ? (okey > key) : (okey < key);
                if (take) key = okey;
            }
        }
        U.mrg.key[tid] = key;
        __syncthreads();
    }

    const int m = scnt < KPRE ? scnt : KPRE;
    for (int i = tid; i < m; i += 512) {
        unsigned long long key = U.mrg.key[i];
        int rel = (int)(key & 0x1FFFu);
        float4 bb = g_bx[p0*CAP + rel];
        U.mrg.x1[i] = bb.x; U.mrg.y1[i] = bb.y;
        U.mrg.x2[i] = bb.z; U.mrg.y2[i] = bb.w;
        U.mrg.area[i] = (bb.z - bb.x) * (bb.w - bb.y);
        U.mrg.logit[i] = __uint_as_float((unsigned)(key >> 32));
    }
    if (tid < 10) {
        int lo = tid * 32;
        unsigned w;
        if (m >= lo + 32) w = 0xFFFFFFFFu;
        else if (m > lo)  w = (1u << (m - lo)) - 1u;
        else              w = 0u;
        keepw[tid] = w;
    }
    __syncthreads();

    // greedy NMS, one round per kept box (<=10); exact prefix argument
    for (int round = 0; round <= KOUT; round++) {
        if (tid < 32) {
            unsigned v = (tid < 10) ? keepw[tid] : 0u;
            unsigned nz = __ballot_sync(0xFFFFFFFFu, v != 0u);
            int w = __ffs(nz) - 1;
            unsigned vw = __shfl_sync(0xFFFFFFFFu, v, (w < 0) ? 0 : w);
            if (tid == 0) s_next = nz ? (w*32 + __ffs(vw) - 1) : -1;
        }
        __syncthreads();
        int i = s_next;
        if (i < 0 || s_nk >= KOUT) break;

        float bx1 = U.mrg.x1[i], by1 = U.mrg.y1[i];
        float bx2 = U.mrg.x2[i], by2 = U.mrg.y2[i];
        float ba  = U.mrg.area[i];

        if (tid == 0) {
            int nk = s_nk;
            float sc = 1.0f / (1.0f + expf(-U.mrg.logit[i]));
            int s5 = b*200 + (lvl*10 + nk)*5;
            out[s5+0] = bx1; out[s5+1] = by1;
            out[s5+2] = bx2; out[s5+3] = by2;
            out[s5+4] = sc;
            if (vF) out[3200 + slot0 + nk] = 1.0f;
            else    vB[slot0 + nk] = 1;
            s_nk = nk + 1;
            atomicAnd(&keepw[i >> 5], ~(1u << (i & 31)));
        }
        if (tid > i && tid < m && ((keepw[tid >> 5] >> (tid & 31)) & 1u)) {
            float ix1 = fmaxf(bx1, U.mrg.x1[tid]);
            float iy1 = fmaxf(by1, U.mrg.y1[tid]);
            float ix2 = fminf(bx2, U.mrg.x2[tid]);
            float iy2 = fminf(by2, U.mrg.y2[tid]);
            float iw = fmaxf(ix2 - ix1, 0.0f), ih = fmaxf(iy2 - iy1, 0.0f);
            float inter = iw * ih;
            float iou = inter / (ba + U.mrg.area[tid] - inter + 1e-9f);
            if (iou > 0.3f) atomicAnd(&keepw[tid >> 5], ~(1u << (tid & 31)));
        }
        __syncthreads();
    }
}

// ---------------------------------------------------------------------------
extern "C" void kernel_launch(void* const* d_in, const int* in_sizes, int n_in,
                              void* d_out, int out_size) {
    Ptrs P;
    if (n_in >= 2 && in_sizes[0] == 2359296 && in_sizes[1] == 9437184) {
        for (int l = 0; l < 4; l++) {
            P.cls[l] = (const float*)d_in[3*l + 0];
            P.box[l] = (const float*)d_in[3*l + 1];
            P.anc[l] = (const float*)d_in[3*l + 2];
        }
    } else if (n_in >= 1 && in_sizes[0] == 2359296) {
        for (int l = 0; l < 4; l++) {
            P.cls[l] = (const float*)d_in[l];
            P.box[l] = (const float*)d_in[4 + l];
            P.anc[l] = (const float*)d_in[8 + l];
        }
    } else {
        for (int l = 0; l < 4; l++) {
            P.anc[l] = (const float*)d_in[l];
            P.box[l] = (const float*)d_in[4 + l];
            P.cls[l] = (const float*)d_in[8 + l];
        }
    }
    detect_kernel<<<NPARTS, 512>>>(P, (float*)d_out, out_size);
}